// round 16
// baseline (speedup 1.0000x reference)
#include <cuda_runtime.h>
#include <math.h>

// ---------------- device scratch (no allocation allowed) ----------------
__device__ __align__(16) float g_v1[256];
__device__ __align__(16) float g_v2[256];
__device__ float g_p1[128];
__device__ float g_p2[128];
__device__ volatile int g_vflag;   // v-blocks done counter (monotone across replays)
__device__ volatile int g_pflag;   // pos-blocks done counter

#define NV_BLOCKS  32
#define NP_BLOCKS  64

// ---------------- single merged kernel ----------------------------------
// ids [0,32): v-blocks, [32,96): pos-blocks (2 positions each), [96,2144): gat
__global__ void __launch_bounds__(256) gat_all_kernel(
    const float* __restrict__ src,
    const float* __restrict__ adj,
    const float* __restrict__ W,
    const float* __restrict__ a,
    float* __restrict__ out)
{
    const int bid = blockIdx.x;
    const int tid = threadIdx.x;

    // ================= v-blocks: g_v1/g_v2 = W @ a1/a2 ==================
    if (bid < NV_BLOCKS) {
        const int l   = tid & 31;
        const int row = bid * 8 + (tid >> 5);

        const float4* Wr = (const float4*)(W + row * 256);
        float4 w0 = __ldg(Wr + 2 * l);
        float4 w1 = __ldg(Wr + 2 * l + 1);
        const float4* A1 = (const float4*)a;
        const float4* A2 = (const float4*)(a + 256);
        float4 p0 = __ldg(A1 + 2 * l), p1 = __ldg(A1 + 2 * l + 1);
        float4 q0 = __ldg(A2 + 2 * l), q1 = __ldg(A2 + 2 * l + 1);

        float acc1 = w0.x * p0.x + w0.y * p0.y + w0.z * p0.z + w0.w * p0.w
                   + w1.x * p1.x + w1.y * p1.y + w1.z * p1.z + w1.w * p1.w;
        float acc2 = w0.x * q0.x + w0.y * q0.y + w0.z * q0.z + w0.w * q0.w
                   + w1.x * q1.x + w1.y * q1.y + w1.z * q1.z + w1.w * q1.w;
#pragma unroll
        for (int off = 16; off; off >>= 1) {
            acc1 += __shfl_xor_sync(0xFFFFFFFFu, acc1, off);
            acc2 += __shfl_xor_sync(0xFFFFFFFFu, acc2, off);
        }
        if (l == 0) { g_v1[row] = acc1; g_v2[row] = acc2; }
        __syncthreads();
        if (tid == 0) { __threadfence(); atomicAdd((int*)&g_vflag, 1); }
        return;
    }

    // ================= pos-blocks: g_p1/g_p2 =============================
    if (bid < NV_BLOCKS + NP_BLOCKS) {
        __shared__ float r1[8], r2[8];
        const int nn = (bid - NV_BLOCKS) * 2 + (tid >> 7);  // position 0..127
        const int p  = tid & 127;                            // pair index
        const int l  = tid & 31;
        const int w  = tid >> 5;                             // 0..7

        if (tid == 0) { while (g_vflag < NV_BLOCKS) {} __threadfence(); }
        __syncthreads();

        // invd[p] = 10^(-p/32), exact 7-bit constant product (no pow)
        const double C0 = 0.9305720409297085428;   // 10^(-1/32)
        const double C1 = 0.8659643233600653549;   // 10^(-1/16)
        const double C2 = 0.7498942093324558866;   // 10^(-1/8)
        const double C3 = 0.5623413251903490803;   // 10^(-1/4)
        const double C4 = 0.3162277660168379332;   // 10^(-1/2)
        const double C5 = 0.1;                     // 10^(-1)
        const double C6 = 0.01;                    // 10^(-2)
        double invd = 1.0;
        if (p & 1)  invd *= C0;
        if (p & 2)  invd *= C1;
        if (p & 4)  invd *= C2;
        if (p & 8)  invd *= C3;
        if (p & 16) invd *= C4;
        if (p & 32) invd *= C5;
        if (p & 64) invd *= C6;

        const double TWO_PI     = 6.283185307179586476925286766559;
        const double INV_TWO_PI = 0.15915494309189533576888376337251;
        double ad = (double)nn * invd;
        double k = rint(ad * INV_TWO_PI);
        float red = (float)(ad - k * TWO_PI);
        float s, c;
        __sincosf(red, &s, &c);

        float t1 = s * g_v1[2 * p] + c * g_v1[2 * p + 1];
        float t2 = s * g_v2[2 * p] + c * g_v2[2 * p + 1];
#pragma unroll
        for (int off = 16; off; off >>= 1) {
            t1 += __shfl_xor_sync(0xFFFFFFFFu, t1, off);
            t2 += __shfl_xor_sync(0xFFFFFFFFu, t2, off);
        }
        if (l == 0) { r1[w] = t1; r2[w] = t2; }
        __syncthreads();
        if ((tid & 127) == 0) {
            const int base = (tid >> 7) * 4;
            g_p1[nn] = 1000.0f * (r1[base] + r1[base + 1] + r1[base + 2] + r1[base + 3]);
            g_p2[nn] = 1000.0f * (r2[base] + r2[base + 1] + r2[base + 2] + r2[base + 3]);
        }
        __syncthreads();
        if (tid == 0) { __threadfence(); atomicAdd((int*)&g_pflag, 1); }
        return;
    }

    // ================= gat-blocks: 1 per batch ===========================
    __shared__ float s1s[128], s2s[128];
    __shared__ float elt[128], elu[128];
    __shared__ __align__(16) float redS[8][128];
    __shared__ float invS[128];
    __shared__ float addS[128];

    const int b = bid - (NV_BLOCKS + NP_BLOCKS);
    const int w = tid >> 5;
    const int l = tid & 31;

    // wait for v (wave-1 blocks spin ~1us; later waves pass immediately)
    if (tid == 0) { while (g_vflag < NV_BLOCKS) {} __threadfence(); }
    __syncthreads();

    // -- phase A: raw dots (p1/p2 added in phase B) --
    const float4* v1p = (const float4*)g_v1;
    const float4* v2p = (const float4*)g_v2;
    float4 v1a = v1p[l], v1b = v1p[l + 32];
    float4 v2a = v2p[l], v2b = v2p[l + 32];

    const float4* sbase = (const float4*)(src + (size_t)b * 32768);
#pragma unroll 2
    for (int r = 0; r < 16; r++) {
        int n = w * 16 + r;
        float4 x0 = __ldcs(sbase + n * 64 + l);
        float4 x1 = __ldcs(sbase + n * 64 + 32 + l);
        float acc1 = x0.x * v1a.x + x0.y * v1a.y + x0.z * v1a.z + x0.w * v1a.w
                   + x1.x * v1b.x + x1.y * v1b.y + x1.z * v1b.z + x1.w * v1b.w;
        float acc2 = x0.x * v2a.x + x0.y * v2a.y + x0.z * v2a.z + x0.w * v2a.w
                   + x1.x * v2b.x + x1.y * v2b.y + x1.z * v2b.z + x1.w * v2b.w;
#pragma unroll
        for (int off = 16; off; off >>= 1) {
            acc1 += __shfl_xor_sync(0xFFFFFFFFu, acc1, off);
            acc2 += __shfl_xor_sync(0xFFFFFFFFu, acc2, off);
        }
        if (l == 0) { s1s[n] = acc1; s2s[n] = acc2; }
    }

    // wait for pos (finished long ago by now)
    if (tid == 0) { while (g_pflag < NP_BLOCKS) {} __threadfence(); }
    __syncthreads();

    // -- phase B: exp(leaky(.)) with pos added here (same FP order) --
    if (tid < 128) {
        int m = tid;
        float s1m = s1s[m] + g_p1[m];
        float s2m = s2s[m] + g_p2[m];
        float t = s1m + s2m;
        t = (t > 0.f) ? t : 0.2f * t;
        elt[m] = expf(t);
        int q0 = (2 * m) & 127, q1 = (2 * m + 1) & 127;
        float u = (s1s[q0] + g_p1[q0]) + (s2s[q1] + g_p2[q1]);
        u = (u > 0.f) ? u : 0.2f * u;
        elu[m] = expf(u);
    }
    __syncthreads();

    // -- phase C: float4 adj loads; thread = (jgroup g, row-slice r8) --
    const int g  = tid & 31;
    const int r8 = tid >> 5;
    const int j0 = g << 2;
    const float4* adjb = (const float4*)(adj + (size_t)b * 16384) + r8 * 16 * 32 + g;

    unsigned m01 = 0, m23 = 0;
    float S0 = 0.f, S1 = 0.f, S2 = 0.f, S3 = 0.f;
    if (r8 < 4) {
        const int jhi = g >> 4;
        const int ibase = r8 * 16;
#pragma unroll
        for (int rr = 0; rr < 16; rr++) {
            float4 av = __ldcs(adjb + rr * 32);
            float ev = elt[2 * (ibase + rr) + jhi];
            if (av.x > 0.f) { m01 |= 1u << rr;        S0 += ev; }
            if (av.y > 0.f) { m01 |= 1u << (16 + rr); S1 += ev; }
            if (av.z > 0.f) { m23 |= 1u << rr;        S2 += ev; }
            if (av.w > 0.f) { m23 |= 1u << (16 + rr); S3 += ev; }
        }
    } else {
        int c0 = 0, c1 = 0, c2 = 0, c3 = 0;
#pragma unroll
        for (int rr = 0; rr < 16; rr++) {
            float4 av = __ldcs(adjb + rr * 32);
            if (av.x > 0.f) { m01 |= 1u << rr;        c0++; }
            if (av.y > 0.f) { m01 |= 1u << (16 + rr); c1++; }
            if (av.z > 0.f) { m23 |= 1u << rr;        c2++; }
            if (av.w > 0.f) { m23 |= 1u << (16 + rr); c3++; }
        }
        S0 = (float)c0 * elu[j0];
        S1 = (float)c1 * elu[j0 + 1];
        S2 = (float)c2 * elu[j0 + 2];
        S3 = (float)c3 * elu[j0 + 3];
    }
    ((float4*)redS[r8])[g] = make_float4(S0, S1, S2, S3);
    __syncthreads();

    if (tid < 128) {
        float s = 0.f;
#pragma unroll
        for (int r = 0; r < 8; r++) s += redS[r][tid];
        invS[tid] = (s > 0.f) ? (1.0f / s) : 0.f;
        addS[tid] = (s > 0.f) ? 0.f : 0.0078125f;
    }
    __syncthreads();

    // -- phase D: float4 write-out (streaming stores) --
    const float i0 = invS[j0],     i1 = invS[j0 + 1];
    const float i2 = invS[j0 + 2], i3 = invS[j0 + 3];
    const float a0 = addS[j0],     a1 = addS[j0 + 1];
    const float a2 = addS[j0 + 2], a3 = addS[j0 + 3];
    float4* outp = (float4*)(out + (size_t)b * 16384) + r8 * 16 * 32 + g;

    if (r8 < 4) {
        const int jhi = g >> 4;
        const int ibase = r8 * 16;
#pragma unroll
        for (int rr = 0; rr < 16; rr++) {
            float ev = elt[2 * (ibase + rr) + jhi];
            float4 v;
            v.x = (((m01 >> rr) & 1u)        ? ev * i0 : 0.f) + a0;
            v.y = (((m01 >> (16 + rr)) & 1u) ? ev * i1 : 0.f) + a1;
            v.z = (((m23 >> rr) & 1u)        ? ev * i2 : 0.f) + a2;
            v.w = (((m23 >> (16 + rr)) & 1u) ? ev * i3 : 0.f) + a3;
            __stcs(outp + rr * 32, v);
        }
    } else {
        const float e0 = elu[j0] * i0,     e1 = elu[j0 + 1] * i1;
        const float e2 = elu[j0 + 2] * i2, e3 = elu[j0 + 3] * i3;
#pragma unroll
        for (int rr = 0; rr < 16; rr++) {
            float4 v;
            v.x = (((m01 >> rr) & 1u)        ? e0 : 0.f) + a0;
            v.y = (((m01 >> (16 + rr)) & 1u) ? e1 : 0.f) + a1;
            v.z = (((m23 >> rr) & 1u)        ? e2 : 0.f) + a2;
            v.w = (((m23 >> (16 + rr)) & 1u) ? e3 : 0.f) + a3;
            __stcs(outp + rr * 32, v);
        }
    }
}

// ---------------- launcher ----------------
extern "C" void kernel_launch(void* const* d_in, const int* in_sizes, int n_in,
                              void* d_out, int out_size) {
    const float* src = (const float*)d_in[0];   // (2048,128,256)
    const float* W   = (const float*)d_in[1];   // (256,256)
    const float* a   = (const float*)d_in[2];   // (512,1)
    const float* adj = (const float*)d_in[3];   // (2048,128,128)
    float* out = (float*)d_out;                 // (2048,128,128)

    gat_all_kernel<<<NV_BLOCKS + NP_BLOCKS + 2048, 256>>>(src, adj, W, a, out);
}

// round 17
// speedup vs baseline: 1.0028x; 1.0028x over previous
#include <cuda_runtime.h>
#include <math.h>

// ---------------- device scratch (no allocation allowed) ----------------
__device__ __align__(16) float g_v1[256];
__device__ __align__(16) float g_v2[256];
__device__ float g_p1[128];
__device__ float g_p2[128];
__device__ volatile int g_vflag;   // v-blocks done counter (monotone across replays)
__device__ volatile int g_pflag;   // pos-blocks done counter

#define NV_BLOCKS  32
#define NP_BLOCKS  64

// ---------------- single merged kernel ----------------------------------
// ids [0,32): v-blocks, [32,96): pos-blocks (2 positions each), [96,2144): gat
__global__ void __launch_bounds__(256) gat_all_kernel(
    const float* __restrict__ src,
    const float* __restrict__ adj,
    const float* __restrict__ W,
    const float* __restrict__ a,
    float* __restrict__ out)
{
    const int bid = blockIdx.x;
    const int tid = threadIdx.x;

    // ================= v-blocks: g_v1/g_v2 = W @ a1/a2 ==================
    if (bid < NV_BLOCKS) {
        const int l   = tid & 31;
        const int row = bid * 8 + (tid >> 5);

        const float4* Wr = (const float4*)(W + row * 256);
        float4 w0 = __ldg(Wr + 2 * l);
        float4 w1 = __ldg(Wr + 2 * l + 1);
        const float4* A1 = (const float4*)a;
        const float4* A2 = (const float4*)(a + 256);
        float4 p0 = __ldg(A1 + 2 * l), p1 = __ldg(A1 + 2 * l + 1);
        float4 q0 = __ldg(A2 + 2 * l), q1 = __ldg(A2 + 2 * l + 1);

        float acc1 = w0.x * p0.x + w0.y * p0.y + w0.z * p0.z + w0.w * p0.w
                   + w1.x * p1.x + w1.y * p1.y + w1.z * p1.z + w1.w * p1.w;
        float acc2 = w0.x * q0.x + w0.y * q0.y + w0.z * q0.z + w0.w * q0.w
                   + w1.x * q1.x + w1.y * q1.y + w1.z * q1.z + w1.w * q1.w;
#pragma unroll
        for (int off = 16; off; off >>= 1) {
            acc1 += __shfl_xor_sync(0xFFFFFFFFu, acc1, off);
            acc2 += __shfl_xor_sync(0xFFFFFFFFu, acc2, off);
        }
        if (l == 0) { g_v1[row] = acc1; g_v2[row] = acc2; }
        __syncthreads();
        if (tid == 0) { __threadfence(); atomicAdd((int*)&g_vflag, 1); }
        return;
    }

    // ================= pos-blocks: g_p1/g_p2 =============================
    if (bid < NV_BLOCKS + NP_BLOCKS) {
        __shared__ float r1[8], r2[8];
        const int nn = (bid - NV_BLOCKS) * 2 + (tid >> 7);  // position 0..127
        const int p  = tid & 127;                            // pair index
        const int l  = tid & 31;
        const int w  = tid >> 5;                             // 0..7

        if (tid == 0) { while (g_vflag < NV_BLOCKS) {} __threadfence(); }
        __syncthreads();

        // invd[p] = 10^(-p/32), exact 7-bit constant product (no pow)
        const double C0 = 0.9305720409297085428;   // 10^(-1/32)
        const double C1 = 0.8659643233600653549;   // 10^(-1/16)
        const double C2 = 0.7498942093324558866;   // 10^(-1/8)
        const double C3 = 0.5623413251903490803;   // 10^(-1/4)
        const double C4 = 0.3162277660168379332;   // 10^(-1/2)
        const double C5 = 0.1;                     // 10^(-1)
        const double C6 = 0.01;                    // 10^(-2)
        double invd = 1.0;
        if (p & 1)  invd *= C0;
        if (p & 2)  invd *= C1;
        if (p & 4)  invd *= C2;
        if (p & 8)  invd *= C3;
        if (p & 16) invd *= C4;
        if (p & 32) invd *= C5;
        if (p & 64) invd *= C6;

        const double TWO_PI     = 6.283185307179586476925286766559;
        const double INV_TWO_PI = 0.15915494309189533576888376337251;
        double ad = (double)nn * invd;
        double k = rint(ad * INV_TWO_PI);
        float red = (float)(ad - k * TWO_PI);
        float s, c;
        __sincosf(red, &s, &c);

        float t1 = s * g_v1[2 * p] + c * g_v1[2 * p + 1];
        float t2 = s * g_v2[2 * p] + c * g_v2[2 * p + 1];
#pragma unroll
        for (int off = 16; off; off >>= 1) {
            t1 += __shfl_xor_sync(0xFFFFFFFFu, t1, off);
            t2 += __shfl_xor_sync(0xFFFFFFFFu, t2, off);
        }
        if (l == 0) { r1[w] = t1; r2[w] = t2; }
        __syncthreads();
        if ((tid & 127) == 0) {
            const int base = (tid >> 7) * 4;
            g_p1[nn] = 1000.0f * (r1[base] + r1[base + 1] + r1[base + 2] + r1[base + 3]);
            g_p2[nn] = 1000.0f * (r2[base] + r2[base + 1] + r2[base + 2] + r2[base + 3]);
        }
        __syncthreads();
        if (tid == 0) { __threadfence(); atomicAdd((int*)&g_pflag, 1); }
        return;
    }

    // ================= gat-blocks: 1 per batch ===========================
    __shared__ float s1s[128], s2s[128];
    __shared__ float elt[128], elu[128];
    __shared__ __align__(16) float redS[8][128];
    __shared__ float invS[128];
    __shared__ float addS[128];

    const int b = bid - (NV_BLOCKS + NP_BLOCKS);
    const int w = tid >> 5;
    const int l = tid & 31;

    // wait for v (wave-1 blocks spin ~1us; later waves pass immediately)
    if (tid == 0) { while (g_vflag < NV_BLOCKS) {} __threadfence(); }
    __syncthreads();

    // -- phase A: raw dots (p1/p2 added in phase B), unroll 4 for MLP --
    const float4* v1p = (const float4*)g_v1;
    const float4* v2p = (const float4*)g_v2;
    float4 v1a = v1p[l], v1b = v1p[l + 32];
    float4 v2a = v2p[l], v2b = v2p[l + 32];

    const float4* sbase = (const float4*)(src + (size_t)b * 32768);
#pragma unroll 4
    for (int r = 0; r < 16; r++) {
        int n = w * 16 + r;
        float4 x0 = __ldcs(sbase + n * 64 + l);
        float4 x1 = __ldcs(sbase + n * 64 + 32 + l);
        float acc1 = x0.x * v1a.x + x0.y * v1a.y + x0.z * v1a.z + x0.w * v1a.w
                   + x1.x * v1b.x + x1.y * v1b.y + x1.z * v1b.z + x1.w * v1b.w;
        float acc2 = x0.x * v2a.x + x0.y * v2a.y + x0.z * v2a.z + x0.w * v2a.w
                   + x1.x * v2b.x + x1.y * v2b.y + x1.z * v2b.z + x1.w * v2b.w;
#pragma unroll
        for (int off = 16; off; off >>= 1) {
            acc1 += __shfl_xor_sync(0xFFFFFFFFu, acc1, off);
            acc2 += __shfl_xor_sync(0xFFFFFFFFu, acc2, off);
        }
        if (l == 0) { s1s[n] = acc1; s2s[n] = acc2; }
    }

    // wait for pos (finished long ago by now)
    if (tid == 0) { while (g_pflag < NP_BLOCKS) {} __threadfence(); }
    __syncthreads();

    // -- phase B: exp(leaky(.)) with pos added here (same FP order) --
    if (tid < 128) {
        int m = tid;
        float s1m = s1s[m] + g_p1[m];
        float s2m = s2s[m] + g_p2[m];
        float t = s1m + s2m;
        t = (t > 0.f) ? t : 0.2f * t;
        elt[m] = expf(t);
        int q0 = (2 * m) & 127, q1 = (2 * m + 1) & 127;
        float u = (s1s[q0] + g_p1[q0]) + (s2s[q1] + g_p2[q1]);
        u = (u > 0.f) ? u : 0.2f * u;
        elu[m] = expf(u);
    }
    __syncthreads();

    // -- phase C: float4 adj loads; thread = (jgroup g, row-slice r8) --
    const int g  = tid & 31;
    const int r8 = tid >> 5;
    const int j0 = g << 2;
    const float4* adjb = (const float4*)(adj + (size_t)b * 16384) + r8 * 16 * 32 + g;

    unsigned m01 = 0, m23 = 0;
    float S0 = 0.f, S1 = 0.f, S2 = 0.f, S3 = 0.f;
    if (r8 < 4) {
        const int jhi = g >> 4;
        const int ibase = r8 * 16;
#pragma unroll
        for (int rr = 0; rr < 16; rr++) {
            float4 av = __ldcs(adjb + rr * 32);
            float ev = elt[2 * (ibase + rr) + jhi];
            if (av.x > 0.f) { m01 |= 1u << rr;        S0 += ev; }
            if (av.y > 0.f) { m01 |= 1u << (16 + rr); S1 += ev; }
            if (av.z > 0.f) { m23 |= 1u << rr;        S2 += ev; }
            if (av.w > 0.f) { m23 |= 1u << (16 + rr); S3 += ev; }
        }
    } else {
        int c0 = 0, c1 = 0, c2 = 0, c3 = 0;
#pragma unroll
        for (int rr = 0; rr < 16; rr++) {
            float4 av = __ldcs(adjb + rr * 32);
            if (av.x > 0.f) { m01 |= 1u << rr;        c0++; }
            if (av.y > 0.f) { m01 |= 1u << (16 + rr); c1++; }
            if (av.z > 0.f) { m23 |= 1u << rr;        c2++; }
            if (av.w > 0.f) { m23 |= 1u << (16 + rr); c3++; }
        }
        S0 = (float)c0 * elu[j0];
        S1 = (float)c1 * elu[j0 + 1];
        S2 = (float)c2 * elu[j0 + 2];
        S3 = (float)c3 * elu[j0 + 3];
    }
    ((float4*)redS[r8])[g] = make_float4(S0, S1, S2, S3);
    __syncthreads();

    if (tid < 128) {
        float s = 0.f;
#pragma unroll
        for (int r = 0; r < 8; r++) s += redS[r][tid];
        invS[tid] = (s > 0.f) ? (1.0f / s) : 0.f;
        addS[tid] = (s > 0.f) ? 0.f : 0.0078125f;
    }
    __syncthreads();

    // -- phase D: float4 write-out (streaming stores) --
    const float i0 = invS[j0],     i1 = invS[j0 + 1];
    const float i2 = invS[j0 + 2], i3 = invS[j0 + 3];
    const float a0 = addS[j0],     a1 = addS[j0 + 1];
    const float a2 = addS[j0 + 2], a3 = addS[j0 + 3];
    float4* outp = (float4*)(out + (size_t)b * 16384) + r8 * 16 * 32 + g;

    if (r8 < 4) {
        const int jhi = g >> 4;
        const int ibase = r8 * 16;
#pragma unroll
        for (int rr = 0; rr < 16; rr++) {
            float ev = elt[2 * (ibase + rr) + jhi];
            float4 v;
            v.x = (((m01 >> rr) & 1u)        ? ev * i0 : 0.f) + a0;
            v.y = (((m01 >> (16 + rr)) & 1u) ? ev * i1 : 0.f) + a1;
            v.z = (((m23 >> rr) & 1u)        ? ev * i2 : 0.f) + a2;
            v.w = (((m23 >> (16 + rr)) & 1u) ? ev * i3 : 0.f) + a3;
            __stcs(outp + rr * 32, v);
        }
    } else {
        const float e0 = elu[j0] * i0,     e1 = elu[j0 + 1] * i1;
        const float e2 = elu[j0 + 2] * i2, e3 = elu[j0 + 3] * i3;
#pragma unroll
        for (int rr = 0; rr < 16; rr++) {
            float4 v;
            v.x = (((m01 >> rr) & 1u)        ? e0 : 0.f) + a0;
            v.y = (((m01 >> (16 + rr)) & 1u) ? e1 : 0.f) + a1;
            v.z = (((m23 >> rr) & 1u)        ? e2 : 0.f) + a2;
            v.w = (((m23 >> (16 + rr)) & 1u) ? e3 : 0.f) + a3;
            __stcs(outp + rr * 32, v);
        }
    }
}

// ---------------- launcher ----------------
extern "C" void kernel_launch(void* const* d_in, const int* in_sizes, int n_in,
                              void* d_out, int out_size) {
    const float* src = (const float*)d_in[0];   // (2048,128,256)
    const float* W   = (const float*)d_in[1];   // (256,256)
    const float* a   = (const float*)d_in[2];   // (512,1)
    const float* adj = (const float*)d_in[3];   // (2048,128,128)
    float* out = (float*)d_out;                 // (2048,128,128)

    gat_all_kernel<<<NV_BLOCKS + NP_BLOCKS + 2048, 256>>>(src, adj, W, a, out);
}